// round 5
// baseline (speedup 1.0000x reference)
#include <cuda_runtime.h>
#include <cuda_bf16.h>
#include <cstdint>
#include <math.h>

#define HID 2048
#define SEQ 2048
#define NH  16
#define HD  128
#define BATCH 2
#define M_ROWS (BATCH*SEQ)   // 4096

// ---------------------------------------------------------------------------
// Scratch (__device__ globals; no allocation allowed)
// ---------------------------------------------------------------------------
__device__ __nv_bfloat16 g_xh[(size_t)M_ROWS * HID];
__device__ __nv_bfloat16 g_xl[(size_t)M_ROWS * HID];
__device__ __nv_bfloat16 g_wqh[(size_t)HID * HID];
__device__ __nv_bfloat16 g_wql[(size_t)HID * HID];
__device__ __nv_bfloat16 g_wkh[(size_t)HID * HID];
__device__ __nv_bfloat16 g_wkl[(size_t)HID * HID];
__device__ __nv_bfloat16 g_wvh[(size_t)HID * HID];
__device__ __nv_bfloat16 g_wvl[(size_t)HID * HID];
__device__ __nv_bfloat16 g_woh[(size_t)HID * HID];
__device__ __nv_bfloat16 g_wol[(size_t)HID * HID];
__device__ __nv_bfloat16 g_qh[(size_t)M_ROWS * HID];
__device__ __nv_bfloat16 g_ql[(size_t)M_ROWS * HID];
__device__ __nv_bfloat16 g_kh[(size_t)M_ROWS * HID];
__device__ __nv_bfloat16 g_kl[(size_t)M_ROWS * HID];
__device__ __nv_bfloat16 g_vh[(size_t)M_ROWS * HID];
__device__ __nv_bfloat16 g_vl[(size_t)M_ROWS * HID];
__device__ __nv_bfloat16 g_cxh[(size_t)M_ROWS * HID];
__device__ __nv_bfloat16 g_cxl[(size_t)M_ROWS * HID];
__device__ float g_sin[SEQ * (HD/2)];
__device__ float g_cos[SEQ * (HD/2)];

// ---------------------------------------------------------------------------
// helpers
// ---------------------------------------------------------------------------
__device__ __forceinline__ uint32_t smem_to_u32(const void* p) {
    uint32_t a;
    asm("{ .reg .u64 t; cvta.to.shared.u64 t, %1; cvt.u32.u64 %0, t; }"
        : "=r"(a) : "l"(p));
    return a;
}

__device__ __forceinline__ void cp16(uint32_t dst, const void* src) {
    asm volatile("cp.async.cg.shared.global [%0], [%1], 16;"
                 :: "r"(dst), "l"(src) : "memory");
}

__device__ __forceinline__ void ldsm_x4(uint32_t* r, uint32_t addr) {
    asm volatile("ldmatrix.sync.aligned.m8n8.x4.shared.b16 {%0,%1,%2,%3}, [%4];"
                 : "=r"(r[0]), "=r"(r[1]), "=r"(r[2]), "=r"(r[3]) : "r"(addr));
}

__device__ __forceinline__ void ldsm_x4_t(uint32_t* r, uint32_t addr) {
    asm volatile("ldmatrix.sync.aligned.m8n8.x4.trans.shared.b16 {%0,%1,%2,%3}, [%4];"
                 : "=r"(r[0]), "=r"(r[1]), "=r"(r[2]), "=r"(r[3]) : "r"(addr));
}

__device__ __forceinline__ void mma_bf16(float* c, const uint32_t* a,
                                         uint32_t b0, uint32_t b1) {
    asm volatile(
        "mma.sync.aligned.m16n8k16.row.col.f32.bf16.bf16.f32 "
        "{%0,%1,%2,%3}, {%4,%5,%6,%7}, {%8,%9}, {%0,%1,%2,%3};"
        : "+f"(c[0]), "+f"(c[1]), "+f"(c[2]), "+f"(c[3])
        : "r"(a[0]), "r"(a[1]), "r"(a[2]), "r"(a[3]), "r"(b0), "r"(b1));
}

__device__ __forceinline__ void splitf(float v, __nv_bfloat16& h, __nv_bfloat16& l) {
    h = __float2bfloat16_rn(v);
    l = __float2bfloat16_rn(v - __bfloat162float(h));
}
__device__ __forceinline__ uint32_t pk2(__nv_bfloat16 a, __nv_bfloat16 b) {
    __nv_bfloat162 t = __halves2bfloat162(a, b);
    return *reinterpret_cast<uint32_t*>(&t);
}

// fast 2^t on the FMA pipe (no MUFU). t <= 0 expected; clamped at -30.
// magic-number round + degree-5 Taylor on f in [-0.5, 0.5]; rel err ~2e-6.
__device__ __forceinline__ float fexp2(float t) {
    t = fmaxf(t, -30.0f);
    const float fi = t + 12582912.0f;          // 1.5*2^23: round-to-nearest-int
    const float r  = fi - 12582912.0f;
    const float f  = t - r;
    float p = 1.3333558146e-3f;                // ln^5(2)/120
    p = fmaf(p, f, 9.6181291076e-3f);          // ln^4(2)/24
    p = fmaf(p, f, 5.5504108665e-2f);          // ln^3(2)/6
    p = fmaf(p, f, 2.4022650696e-1f);          // ln^2(2)/2
    p = fmaf(p, f, 6.9314718056e-1f);          // ln(2)
    p = fmaf(p, f, 1.0f);
    const int e = __float_as_int(fi) - 0x4B400000;   // integer value of r
    return __int_as_float(__float_as_int(p) + (e << 23));
}

// ---------------------------------------------------------------------------
// Prep kernels
// ---------------------------------------------------------------------------
__global__ void rope_table_kernel(float* __restrict__ st, float* __restrict__ ct) {
    int idx = blockIdx.x * blockDim.x + threadIdx.x;   // SEQ*64
    int s = idx >> 6, j = idx & 63;
    double f = exp(-0.14391156831212787 * (double)j);  // 10000^(-2j/128)
    double sn, cs;
    sincos((double)s * f, &sn, &cs);
    st[idx] = (float)sn;
    ct[idx] = (float)cs;
}

__global__ void __launch_bounds__(256) split_x_kernel(
    const float4* __restrict__ X, uint2* __restrict__ H, uint2* __restrict__ L)
{
    size_t i = (size_t)blockIdx.x * blockDim.x + threadIdx.x;
    float4 v = X[i];
    __nv_bfloat16 h0, l0, h1, l1, h2, l2, h3, l3;
    splitf(v.x, h0, l0); splitf(v.y, h1, l1);
    splitf(v.z, h2, l2); splitf(v.w, h3, l3);
    H[i] = make_uint2(pk2(h0, h1), pk2(h2, h3));
    L[i] = make_uint2(pk2(l0, l1), pk2(l2, l3));
}

// W [K][N] fp32 -> Wt [N][K] bf16 hi/lo (transpose + split)
__global__ void __launch_bounds__(256) wtrans_kernel(
    const float* __restrict__ W, __nv_bfloat16* __restrict__ Th,
    __nv_bfloat16* __restrict__ Tl)
{
    __shared__ float t[32][33];
    const int n0 = blockIdx.x * 32, k0 = blockIdx.y * 32;
    const int tx = threadIdx.x, ty = threadIdx.y;   // (32, 8)
#pragma unroll
    for (int i = 0; i < 4; i++)
        t[ty + 8 * i][tx] = W[(size_t)(k0 + ty + 8 * i) * HID + n0 + tx];
    __syncthreads();
#pragma unroll
    for (int i = 0; i < 4; i++) {
        float v = t[tx][ty + 8 * i];
        __nv_bfloat16 h, l;
        splitf(v, h, l);
        const size_t o = (size_t)(n0 + ty + 8 * i) * HID + k0 + tx;
        Th[o] = h;
        Tl[o] = l;
    }
}

// ---------------------------------------------------------------------------
// mma.sync split-bf16 GEMM.  BM=BN=128, BK=32, 8 warps, 4-stage cp.async.
// mode 0: fp32 out (+bias); mode 1: bias+RoPE, scaled, split-bf16 out;
// mode 2: bias only, split-bf16 out.
// ---------------------------------------------------------------------------
#define ROWP 40                         // padded row length (bf16 elems)
#define TILE_BYTES (128 * ROWP * 2)     // 10240
#define STAGE_BYTES (2 * TILE_BYTES)
#define STAGES 4
#define GSMEM (STAGES * STAGE_BYTES)    // 81920
#define NVCHUNK (3 * HID / 32)          // 192

__device__ __forceinline__ void gemm_mma_body(
    const __nv_bfloat16* __restrict__ Ah, const __nv_bfloat16* __restrict__ Al,
    const __nv_bfloat16* __restrict__ Bh, const __nv_bfloat16* __restrict__ Bl,
    const float* __restrict__ bias,
    float* __restrict__ Yf, __nv_bfloat16* __restrict__ Yh,
    __nv_bfloat16* __restrict__ Yl, float oscale,
    const float* __restrict__ stab, const float* __restrict__ ctab, int mode)
{
    extern __shared__ __align__(128) char smem[];
    const uint32_t sb = smem_to_u32(smem);
    const int tid = threadIdx.x;
    const int wid = tid >> 5, lane = tid & 31;
    const int warp_m = wid & 3, warp_n = wid >> 2;
    const int bm = blockIdx.y * 128, bn = blockIdx.x * 128;

    const int lrow = tid >> 2, lch = tid & 3;
    const uint32_t dA = sb + lrow * 80 + lch * 16;
    const uint32_t dB = sb + TILE_BYTES + lrow * 80 + lch * 16;
    const int gcol = lch * 8;

    const uint32_t aoff =
        ((warp_m * 32 + ((lane >> 3) & 1) * 8 + (lane & 7)) * ROWP +
         (lane >> 4) * 8) * 2;
    const uint32_t boff =
        ((warp_n * 64 + ((lane >> 4) & 1) * 8 + (lane & 7)) * ROWP +
         ((lane >> 3) & 1) * 8) * 2;
    const uint32_t aBase = sb + aoff;
    const uint32_t bBase = sb + TILE_BYTES + boff;

    float acc[2][8][4];
#pragma unroll
    for (int mt = 0; mt < 2; mt++)
#pragma unroll
        for (int nt = 0; nt < 8; nt++)
#pragma unroll
            for (int e = 0; e < 4; e++) acc[mt][nt][e] = 0.0f;

    auto issue = [&](int cv, int stage) {
        const int prod = cv >> 6;
        const int k0 = (cv & 63) << 5;
        const __nv_bfloat16* As = (prod == 1) ? Al : Ah;
        const __nv_bfloat16* Bs = (prod == 2) ? Bl : Bh;
        const __nv_bfloat16* ap = As + (size_t)(bm + lrow) * HID + k0 + gcol;
        const __nv_bfloat16* bp = Bs + (size_t)(bn + lrow) * HID + k0 + gcol;
        const uint32_t so = stage * STAGE_BYTES;
        cp16(dA + so, ap);
        cp16(dA + so + 64 * 80, ap + (size_t)64 * HID);
        cp16(dB + so, bp);
        cp16(dB + so + 64 * 80, bp + (size_t)64 * HID);
    };

#pragma unroll
    for (int s = 0; s < STAGES; s++) {
        issue(s, s);
        asm volatile("cp.async.commit_group;" ::: "memory");
    }

    for (int cv = 0; cv < NVCHUNK; cv++) {
        asm volatile("cp.async.wait_group 3;" ::: "memory");
        __syncthreads();
        const uint32_t so = (cv & 3) * STAGE_BYTES;
#pragma unroll
        for (int ks = 0; ks < 2; ks++) {
            uint32_t a[2][4], b[4][4];
#pragma unroll
            for (int mt = 0; mt < 2; mt++)
                ldsm_x4(a[mt], aBase + so + mt * (16 * ROWP * 2) + ks * 32);
#pragma unroll
            for (int nb = 0; nb < 4; nb++)
                ldsm_x4(b[nb], bBase + so + nb * (16 * ROWP * 2) + ks * 32);
#pragma unroll
            for (int mt = 0; mt < 2; mt++)
#pragma unroll
                for (int nt = 0; nt < 8; nt++) {
                    const uint32_t* bb = b[nt >> 1];
                    if (nt & 1) mma_bf16(acc[mt][nt], a[mt], bb[2], bb[3]);
                    else        mma_bf16(acc[mt][nt], a[mt], bb[0], bb[1]);
                }
        }
        __syncthreads();
        if (cv + STAGES < NVCHUNK) issue(cv + STAGES, cv & 3);
        asm volatile("cp.async.commit_group;" ::: "memory");
    }

    const int r0 = bm + warp_m * 32 + (lane >> 2);
    const int c0base = bn + warp_n * 64 + (lane & 3) * 2;
#pragma unroll
    for (int mt = 0; mt < 2; mt++) {
#pragma unroll
        for (int half = 0; half < 2; half++) {
            const int row = r0 + mt * 16 + half * 8;
            const int s = row & (SEQ - 1);
#pragma unroll
            for (int nt = 0; nt < 8; nt++) {
                const int col = c0base + nt * 8;
                float e  = acc[mt][nt][half * 2 + 0] + bias[col];
                float od = acc[mt][nt][half * 2 + 1] + bias[col + 1];
                if (mode == 1) {
                    const int j = (col & (HD - 1)) >> 1;
                    const float sn = stab[(s << 6) + j];
                    const float cs = ctab[(s << 6) + j];
                    float re = e * cs - od * sn;
                    float ro = od * cs + e * sn;
                    e = re * oscale;
                    od = ro * oscale;
                }
                if (mode == 0) {
                    float2 r;
                    r.x = e; r.y = od;
                    *(float2*)(Yf + (size_t)row * HID + col) = r;
                } else {
                    __nv_bfloat16 h0, l0, h1, l1;
                    splitf(e, h0, l0);
                    splitf(od, h1, l1);
                    *(uint32_t*)(Yh + (size_t)row * HID + col) = pk2(h0, h1);
                    *(uint32_t*)(Yl + (size_t)row * HID + col) = pk2(l0, l1);
                }
            }
        }
    }
}

// Q scale folds softmax 1/sqrt(128) AND log2(e) (softmax done in base-2)
#define QSCALE (0.08838834764831843f * 1.4426950408889634f)

__global__ void __launch_bounds__(256, 2) mma_gemm_qkv_kernel(
    const __nv_bfloat16* xh, const __nv_bfloat16* xl,
    const __nv_bfloat16* wqh, const __nv_bfloat16* wql,
    const __nv_bfloat16* wkh, const __nv_bfloat16* wkl,
    const __nv_bfloat16* wvh, const __nv_bfloat16* wvl,
    const float* bq, const float* bk, const float* bv,
    __nv_bfloat16* qh, __nv_bfloat16* ql,
    __nv_bfloat16* kh, __nv_bfloat16* kl,
    __nv_bfloat16* vh, __nv_bfloat16* vl,
    const float* stab, const float* ctab)
{
    if (blockIdx.z == 0)
        gemm_mma_body(xh, xl, wqh, wql, bq, nullptr, qh, ql,
                      QSCALE, stab, ctab, 1);
    else if (blockIdx.z == 1)
        gemm_mma_body(xh, xl, wkh, wkl, bk, nullptr, kh, kl, 1.0f, stab, ctab, 1);
    else
        gemm_mma_body(xh, xl, wvh, wvl, bv, nullptr, vh, vl, 1.0f, nullptr, nullptr, 2);
}

__global__ void __launch_bounds__(256, 2) mma_gemm_out_kernel(
    const __nv_bfloat16* ah, const __nv_bfloat16* al,
    const __nv_bfloat16* wh, const __nv_bfloat16* wl,
    const float* bo, float* Y)
{
    gemm_mma_body(ah, al, wh, wl, bo, Y, nullptr, nullptr, 1.0f, nullptr, nullptr, 0);
}

// ---------------------------------------------------------------------------
// Flash attention v2: tensor-core split-bf16, base-2 softmax on the FMA pipe.
// Br=128, Bc=64, 8 warps. Warp w owns Q rows [16w, 16w+16).
// ---------------------------------------------------------------------------
#define BR 128
#define BC 64
#define RQ 136                  // padded row (bf16 elems); 272B
#define RB (RQ*2)
#define QBYTES (BR*RB)          // 34816
#define QTOT (2*QBYTES)         // 69632
#define KVSTG (4*BC*RB)         // 69632
#define FL2_SMEM (QTOT + 2*KVSTG)   // 208896
#define NKT (SEQ/BC)            // 32

__global__ void __launch_bounds__(256, 1) flash2_kernel(
    const __nv_bfloat16* __restrict__ Qh, const __nv_bfloat16* __restrict__ Ql,
    const __nv_bfloat16* __restrict__ Kh, const __nv_bfloat16* __restrict__ Kl,
    const __nv_bfloat16* __restrict__ Vh, const __nv_bfloat16* __restrict__ Vl,
    __nv_bfloat16* __restrict__ CtxH, __nv_bfloat16* __restrict__ CtxL)
{
    extern __shared__ __align__(128) char smem[];
    const uint32_t sb = smem_to_u32(smem);
    const int tid = threadIdx.x;
    const int wid = tid >> 5, lane = tid & 31;
    const int bh = blockIdx.y;
    const int b = bh >> 4, h = bh & 15;
    const int q0 = blockIdx.x * BR;
    const size_t rowbase = (size_t)b * SEQ;
    const int coff = h * HD;

    {
        const int row = tid >> 1;
        const int ch0 = (tid & 1) * 8;
        const size_t gq = (rowbase + q0 + row) * HID + coff;
        const __nv_bfloat16* sh = Qh + gq;
        const __nv_bfloat16* sl = Ql + gq;
#pragma unroll
        for (int c = 0; c < 8; c++) {
            const int ch = ch0 + c;
            cp16(sb + row * RB + ch * 16, sh + ch * 8);
            cp16(sb + QBYTES + row * RB + ch * 16, sl + ch * 8);
        }
    }

    auto issue_kv = [&](int kt, int stg) {
        const int row = tid >> 2;
        const int cq = tid & 3;
        const size_t g = (rowbase + (size_t)kt * BC + row) * HID + coff;
        const uint32_t base = sb + QTOT + stg * KVSTG + row * RB;
#pragma unroll
        for (int c = 0; c < 4; c++) {
            const int ch = cq + c * 4;
            cp16(base + ch * 16,         Kh + g + ch * 8);
            cp16(base + 17408 + ch * 16, Kl + g + ch * 8);
            cp16(base + 34816 + ch * 16, Vh + g + ch * 8);
            cp16(base + 52224 + ch * 16, Vl + g + ch * 8);
        }
    };

    issue_kv(0, 0);
    asm volatile("cp.async.commit_group;" ::: "memory");

    // softmax state in log2 domain
    float m0 = -1e30f, m1 = -1e30f, l0 = 0.0f, l1 = 0.0f;
    float oacc[16][4];
#pragma unroll
    for (int nt = 0; nt < 16; nt++)
#pragma unroll
        for (int e = 0; e < 4; e++) oacc[nt][e] = 0.0f;

    const uint32_t qBh = sb + (wid * 16 + (lane & 15)) * RB + ((lane >> 4) * 8) * 2;
    const uint32_t qBl = qBh + QBYTES;
    const uint32_t kRel = (((lane >> 4) & 1) * 8 + (lane & 7)) * RB +
                          (((lane >> 3) & 1) * 8) * 2;
    const uint32_t vRel = (lane & 15) * RB + ((lane >> 4) * 8) * 2;

    for (int kt = 0; kt < NKT; kt++) {
        if (kt + 1 < NKT) {
            issue_kv(kt + 1, (kt + 1) & 1);
            asm volatile("cp.async.commit_group;" ::: "memory");
            asm volatile("cp.async.wait_group 1;" ::: "memory");
        } else {
            asm volatile("cp.async.wait_group 0;" ::: "memory");
        }
        __syncthreads();

        const uint32_t kb = sb + QTOT + (kt & 1) * KVSTG;

        // ---- S = Q K^T (split bf16, 3 products); log2-domain scores ----
        float sacc[8][4];
#pragma unroll
        for (int nt = 0; nt < 8; nt++)
#pragma unroll
            for (int e = 0; e < 4; e++) sacc[nt][e] = 0.0f;

#pragma unroll
        for (int ks = 0; ks < 8; ks++) {
            uint32_t qa[4], ql4[4];
            ldsm_x4(qa, qBh + ks * 32);
            ldsm_x4(ql4, qBl + ks * 32);
#pragma unroll
            for (int ng = 0; ng < 4; ng++) {
                uint32_t bh4[4], bl4[4];
                const uint32_t ka = kb + kRel + ng * (16 * RB) + ks * 32;
                ldsm_x4(bh4, ka);
                ldsm_x4(bl4, ka + 17408);
                mma_bf16(sacc[2 * ng],     qa,  bh4[0], bh4[1]);
                mma_bf16(sacc[2 * ng],     ql4, bh4[0], bh4[1]);
                mma_bf16(sacc[2 * ng],     qa,  bl4[0], bl4[1]);
                mma_bf16(sacc[2 * ng + 1], qa,  bh4[2], bh4[3]);
                mma_bf16(sacc[2 * ng + 1], ql4, bh4[2], bh4[3]);
                mma_bf16(sacc[2 * ng + 1], qa,  bl4[2], bl4[3]);
            }
        }

        // ---- online softmax, base-2, FMA-pipe exp ----
        float mx0 = -1e30f, mx1 = -1e30f;
#pragma unroll
        for (int nt = 0; nt < 8; nt++) {
            mx0 = fmaxf(mx0, fmaxf(sacc[nt][0], sacc[nt][1]));
            mx1 = fmaxf(mx1, fmaxf(sacc[nt][2], sacc[nt][3]));
        }
        mx0 = fmaxf(mx0, __shfl_xor_sync(0xffffffffu, mx0, 1));
        mx0 = fmaxf(mx0, __shfl_xor_sync(0xffffffffu, mx0, 2));
        mx1 = fmaxf(mx1, __shfl_xor_sync(0xffffffffu, mx1, 1));
        mx1 = fmaxf(mx1, __shfl_xor_sync(0xffffffffu, mx1, 2));

        const float mn0 = fmaxf(m0, mx0);
        const float mn1 = fmaxf(m1, mx1);
        const float corr0 = fexp2(m0 - mn0);
        const float corr1 = fexp2(m1 - mn1);
        m0 = mn0;
        m1 = mn1;

        uint32_t ph0[8], ph1[8], pl0[8], pl1[8];
        float rs0 = 0.0f, rs1 = 0.0f;
#pragma unroll
        for (int nt = 0; nt < 8; nt++) {
            float p00 = fexp2(sacc[nt][0] - mn0);
            float p01 = fexp2(sacc[nt][1] - mn0);
            float p10 = fexp2(sacc[nt][2] - mn1);
            float p11 = fexp2(sacc[nt][3] - mn1);
            rs0 += p00 + p01;
            rs1 += p10 + p11;
            __nv_bfloat16 a, bb, c, d;
            splitf(p00, a, bb); splitf(p01, c, d);
            ph0[nt] = pk2(a, c); pl0[nt] = pk2(bb, d);
            splitf(p10, a, bb); splitf(p11, c, d);
            ph1[nt] = pk2(a, c); pl1[nt] = pk2(bb, d);
        }
        rs0 += __shfl_xor_sync(0xffffffffu, rs0, 1);
        rs0 += __shfl_xor_sync(0xffffffffu, rs0, 2);
        rs1 += __shfl_xor_sync(0xffffffffu, rs1, 1);
        rs1 += __shfl_xor_sync(0xffffffffu, rs1, 2);
        l0 = l0 * corr0 + rs0;
        l1 = l1 * corr1 + rs1;

#pragma unroll
        for (int nt = 0; nt < 16; nt++) {
            oacc[nt][0] *= corr0;
            oacc[nt][1] *= corr0;
            oacc[nt][2] *= corr1;
            oacc[nt][3] *= corr1;
        }

        // ---- O += P V (split bf16, 3 products; V via ldmatrix.trans) ----
        const uint32_t vb = kb + 34816;
#pragma unroll
        for (int ks2 = 0; ks2 < 4; ks2++) {
            uint32_t ah[4] = {ph0[2 * ks2], ph1[2 * ks2],
                              ph0[2 * ks2 + 1], ph1[2 * ks2 + 1]};
            uint32_t al[4] = {pl0[2 * ks2], pl1[2 * ks2],
                              pl0[2 * ks2 + 1], pl1[2 * ks2 + 1]};
#pragma unroll
            for (int ng = 0; ng < 8; ng++) {
                uint32_t vh4[4], vl4[4];
                const uint32_t va = vb + vRel + ks2 * (16 * RB) + ng * 32;
                ldsm_x4_t(vh4, va);
                ldsm_x4_t(vl4, va + 17408);
                mma_bf16(oacc[2 * ng],     ah, vh4[0], vh4[1]);
                mma_bf16(oacc[2 * ng],     al, vh4[0], vh4[1]);
                mma_bf16(oacc[2 * ng],     ah, vl4[0], vl4[1]);
                mma_bf16(oacc[2 * ng + 1], ah, vh4[2], vh4[3]);
                mma_bf16(oacc[2 * ng + 1], al, vh4[2], vh4[3]);
                mma_bf16(oacc[2 * ng + 1], ah, vl4[2], vl4[3]);
            }
        }
        __syncthreads();
    }

    const float inv0 = 1.0f / l0;
    const float inv1 = 1.0f / l1;
    const size_t row0 = rowbase + q0 + wid * 16 + (lane >> 2);
    const size_t row1 = row0 + 8;
    const int cb = coff + (lane & 3) * 2;
#pragma unroll
    for (int nt = 0; nt < 16; nt++) {
        const int col = cb + nt * 8;
        __nv_bfloat16 h0, lo0, h1, lo1;
        splitf(oacc[nt][0] * inv0, h0, lo0);
        splitf(oacc[nt][1] * inv0, h1, lo1);
        *(uint32_t*)(CtxH + row0 * HID + col) = pk2(h0, h1);
        *(uint32_t*)(CtxL + row0 * HID + col) = pk2(lo0, lo1);
        splitf(oacc[nt][2] * inv1, h0, lo0);
        splitf(oacc[nt][3] * inv1, h1, lo1);
        *(uint32_t*)(CtxH + row1 * HID + col) = pk2(h0, h1);
        *(uint32_t*)(CtxL + row1 * HID + col) = pk2(lo0, lo1);
    }
}

// ---------------------------------------------------------------------------
extern "C" void kernel_launch(void* const* d_in, const int* in_sizes, int n_in,
                              void* d_out, int out_size)
{
    const float* X  = (const float*)d_in[0];
    const float* Wq = (const float*)d_in[1];
    const float* bq = (const float*)d_in[2];
    const float* Wk = (const float*)d_in[3];
    const float* bk = (const float*)d_in[4];
    const float* Wv = (const float*)d_in[5];
    const float* bv = (const float*)d_in[6];
    const float* Wo = (const float*)d_in[7];
    const float* bo = (const float*)d_in[8];
    float* out = (float*)d_out;

    __nv_bfloat16 *xh, *xl, *wqh, *wql, *wkh, *wkl, *wvh, *wvl, *woh, *wol;
    __nv_bfloat16 *qh, *ql, *kh, *kl, *vh, *vl, *cxh, *cxl;
    float *stab, *ctab;
    cudaGetSymbolAddress((void**)&xh,  g_xh);
    cudaGetSymbolAddress((void**)&xl,  g_xl);
    cudaGetSymbolAddress((void**)&wqh, g_wqh);
    cudaGetSymbolAddress((void**)&wql, g_wql);
    cudaGetSymbolAddress((void**)&wkh, g_wkh);
    cudaGetSymbolAddress((void**)&wkl, g_wkl);
    cudaGetSymbolAddress((void**)&wvh, g_wvh);
    cudaGetSymbolAddress((void**)&wvl, g_wvl);
    cudaGetSymbolAddress((void**)&woh, g_woh);
    cudaGetSymbolAddress((void**)&wol, g_wol);
    cudaGetSymbolAddress((void**)&qh,  g_qh);
    cudaGetSymbolAddress((void**)&ql,  g_ql);
    cudaGetSymbolAddress((void**)&kh,  g_kh);
    cudaGetSymbolAddress((void**)&kl,  g_kl);
    cudaGetSymbolAddress((void**)&vh,  g_vh);
    cudaGetSymbolAddress((void**)&vl,  g_vl);
    cudaGetSymbolAddress((void**)&cxh, g_cxh);
    cudaGetSymbolAddress((void**)&cxl, g_cxl);
    cudaGetSymbolAddress((void**)&stab, g_sin);
    cudaGetSymbolAddress((void**)&ctab, g_cos);

    cudaFuncSetAttribute(mma_gemm_qkv_kernel,
                         cudaFuncAttributeMaxDynamicSharedMemorySize, GSMEM);
    cudaFuncSetAttribute(mma_gemm_out_kernel,
                         cudaFuncAttributeMaxDynamicSharedMemorySize, GSMEM);
    cudaFuncSetAttribute(flash2_kernel,
                         cudaFuncAttributeMaxDynamicSharedMemorySize, FL2_SMEM);

    // 0) RoPE sin/cos table
    rope_table_kernel<<<SEQ * 64 / 256, 256>>>(stab, ctab);

    // 1) split X into bf16 hi/lo
    split_x_kernel<<<(int)(((size_t)M_ROWS * HID / 4) / 256), 256>>>(
        (const float4*)X, (uint2*)xh, (uint2*)xl);

    // 2) transpose + split weights
    {
        dim3 g(HID / 32, HID / 32), blk(32, 8);
        wtrans_kernel<<<g, blk>>>(Wq, wqh, wql);
        wtrans_kernel<<<g, blk>>>(Wk, wkh, wkl);
        wtrans_kernel<<<g, blk>>>(Wv, wvh, wvl);
        wtrans_kernel<<<g, blk>>>(Wo, woh, wol);
    }

    // 3) QKV projections + bias + RoPE -> split-bf16 q/k/v
    //    (q additionally scaled by 1/sqrt(128)*log2(e) for base-2 softmax)
    {
        dim3 grid(HID / 128, M_ROWS / 128, 3);
        mma_gemm_qkv_kernel<<<grid, 256, GSMEM>>>(
            xh, xl, wqh, wql, wkh, wkl, wvh, wvl, bq, bk, bv,
            qh, ql, kh, kl, vh, vl, stab, ctab);
    }

    // 4) flash attention (tensor cores, base-2 softmax) -> split-bf16 context
    {
        dim3 grid(SEQ / BR, BATCH * NH);
        flash2_kernel<<<grid, 256, FL2_SMEM>>>(qh, ql, kh, kl, vh, vl, cxh, cxl);
    }

    // 5) output projection + bias -> out
    {
        dim3 grid(HID / 128, M_ROWS / 128);
        mma_gemm_out_kernel<<<grid, 256, GSMEM>>>(cxh, cxl, woh, wol, bo, out);
    }
}